// round 17
// baseline (speedup 1.0000x reference)
#include <cuda_runtime.h>
#include <cuda_fp16.h>
#include <cstdint>

// ---------------------------------------------------------------------------
// Fused LSTMDiscriminator, round 17: R16 with non-volatile MMA asm (pure
// register function) so ptxas can interleave the tile0/tile1 HMMA chains and
// activation MUFUs freely instead of strict program order. ldmatrix / STS
// keep volatile+memory (they touch SMEM across the step barrier).
// ---------------------------------------------------------------------------

#define GATES    512
#define HID      128
#define EMB      64
#define NSEL     512
#define MAXSTEPS 20
#define AG       4
#define PW1      129
#define PW2      65
#define NBLK     (NSEL/AG)   // 128 blocks
#define NTHR     512

// SMEM layout for main kernel (bytes)
#define OFF_XS   0                        // 4096 : h ping-pong [2][128][8] f16
#define OFF_VMT  4096                     // 1280 : float4 (vx,vy,mask,0) [4][20]
#define OFF_SH   5376                     // 2048 : final h fp32 [4][128]
#define OFF_S1   7424                     // 1024
#define OFF_S2   8448                     // 512
#define OFF_W1S  8960                     // 33024: W1 pitch-129
#define OFF_W2S  41984                    // 8320 : W2 pitch-65
#define SMEM_TOTAL 50304

// shared precomputed state (written by prep_kernel each call — deterministic)
__device__ __align__(16) uint4  g_Afrag[16 * 512];        // [j4][tid] frag regs
__device__ __align__(16) float4 g_wc[GATES];              // folded input coefs

__device__ __forceinline__ float tanha(float x) {
    float y;
    asm("tanh.approx.f32 %0, %1;" : "=f"(y) : "f"(x));
    return y;
}
__device__ __forceinline__ float sigf(float x) {
    return fmaf(tanha(0.5f * x), 0.5f, 0.5f);
}

// NOTE: non-volatile — pure register function, scheduler may reorder freely.
__device__ __forceinline__ void mma_acc(float d[4], const uint32_t* a,
                                        uint32_t b0, uint32_t b1) {
    asm("mma.sync.aligned.m16n8k16.row.col.f32.f16.f16.f32 "
        "{%0,%1,%2,%3},{%4,%5,%6,%7},{%8,%9},{%0,%1,%2,%3};"
        : "+f"(d[0]), "+f"(d[1]), "+f"(d[2]), "+f"(d[3])
        : "r"(a[0]), "r"(a[1]), "r"(a[2]), "r"(a[3]), "r"(b0), "r"(b1));
}

// =============================== prep kernel ================================
// blocks 0..15  : A-fragment packing (8192 uint4)
// blocks 16..31 : W_ih fold, 32 gate rows per block (one shot)
__global__ void __launch_bounds__(512) prep_kernel(
    const float* __restrict__ W_emb, const float* __restrict__ b_emb,
    const float* __restrict__ W_ih,  const float* __restrict__ W_hh,
    const float* __restrict__ b_ih,  const float* __restrict__ b_hh)
{
    cudaTriggerProgrammaticLaunchCompletion();

    const int b = blockIdx.x, tid = threadIdx.x;

    if (b < 16) {
        // A-fragment packing in exact per-thread register order.
        // tile0 = gates {i(0), g(2)}, tile1 = {f(1), o(3)}; A{tile}[kc] =
        // {gA[k..k+1], gB[k..k+1], gA[k+8..k+9], gB[k+8..k+9]}, k = kc*16+2q
        const int i     = b * 512 + tid;
        const int tid_m = i & 511;
        const int j4    = i >> 9;
        const int u     = 8 * (tid_m >> 5) + ((tid_m >> 2) & 7);
        const int q     = tid_m & 3;
        const int tile  = j4 >> 3;
        const int kc    = j4 & 7;
        const int gA    = tile ? 1 : 0;
        const int gB    = tile ? 3 : 2;
        const int k     = kc * 16 + 2 * q;
        const float* WA = W_hh + (size_t)(gA * 128 + u) * HID;
        const float* WB = W_hh + (size_t)(gB * 128 + u) * HID;
        __half2 hx = __floats2half2_rn(WA[k],     WA[k + 1]);
        __half2 hy = __floats2half2_rn(WB[k],     WB[k + 1]);
        __half2 hz = __floats2half2_rn(WA[k + 8], WA[k + 9]);
        __half2 hw = __floats2half2_rn(WB[k + 8], WB[k + 9]);
        uint4 o;
        o.x = *(const uint32_t*)&hx;
        o.y = *(const uint32_t*)&hy;
        o.z = *(const uint32_t*)&hz;
        o.w = *(const uint32_t*)&hw;
        g_Afrag[j4 * 512 + tid_m] = o;
    } else {
        // fold W_ih @ W_emb (+bias) — 32 rows per block, one shot
        const int e0  = (tid & 15) << 2;
        const int row = (b - 16) * 32 + (tid >> 4);
        float we0[4], we1[4], be4[4];
        #pragma unroll
        for (int j = 0; j < 4; j++) {
            float2 we = ((const float2*)W_emb)[e0 + j];
            we0[j] = we.x; we1[j] = we.y;
            be4[j] = b_emb[e0 + j];
        }
        float4 v = *(const float4*)(W_ih + (size_t)row * EMB + e0);
        float p0 = v.x*we0[0] + v.y*we0[1] + v.z*we0[2] + v.w*we0[3];
        float p1 = v.x*we1[0] + v.y*we1[1] + v.z*we1[2] + v.w*we1[3];
        float p2 = v.x*be4[0] + v.y*be4[1] + v.z*be4[2] + v.w*be4[3];
        #pragma unroll
        for (int mdist = 8; mdist >= 1; mdist >>= 1) {
            p0 += __shfl_xor_sync(0xffffffffu, p0, mdist);
            p1 += __shfl_xor_sync(0xffffffffu, p1, mdist);
            p2 += __shfl_xor_sync(0xffffffffu, p2, mdist);
        }
        if ((tid & 15) == 0) {
            float bc = p2 + b_ih[row] + b_hh[row];
            g_wc[row] = make_float4(4.0f * p0, 4.0f * p1, bc, 0.f);
        }
    }
}

// =============================== main kernel ================================
__global__ void __launch_bounds__(NTHR, 1) fused_kernel(
    const float* __restrict__ obs, const float* __restrict__ pred,
    const void*  __restrict__ bsplit,
    const float* __restrict__ W1, const float* __restrict__ b1,
    const float* __restrict__ W2, const float* __restrict__ b2,
    const float* __restrict__ W3, const float* __restrict__ b3,
    float* __restrict__ out,
    int N, int T_obs, int steps)
{
    extern __shared__ char smraw[];
    __half*  Xs    = (__half*) (smraw + OFF_XS);   // [2][128][8]
    float4*  s_vmt = (float4*) (smraw + OFF_VMT);  // [agent][t]
    float*   sh    = (float*)  (smraw + OFF_SH);
    float*   s1    = (float*)  (smraw + OFF_S1);
    float*   s2    = (float*)  (smraw + OFF_S2);
    float*   W1s   = (float*)  (smraw + OFF_W1S);
    float*   W2s   = (float*)  (smraw + OFF_W2S);

    const int tid  = threadIdx.x;
    const int w    = tid >> 5;
    const int lane = tid & 31;
    const int r    = lane >> 2;
    const int q    = lane & 3;           // agent owned by this thread
    const int row0 = blockIdx.x * AG;
    const int u    = 8 * w + r;          // hidden unit owned by this thread

    // ===== independent prologue (overlaps prep kernel via PDL) ============
    // (a) velocity/mask gather for this block's 4 agents
    if (tid < AG * steps) {
        const int a = tid / steps;
        const int t = tid - a * steps;
        const int row = row0 + a;
        const int* p32 = (const int*)bsplit;       // dtype-robust int32/int64
        int agent = (p32[NSEL] == N) ? p32[row]
                                     : (int)((const long long*)bsplit)[row];
        const float* f0 = (t < T_obs)
            ? obs  + ((size_t)t * N + agent) * 2
            : pred + ((size_t)(t - T_obs) * N + agent) * 2;
        int t1 = t + 1;
        const float* f1 = (t1 < T_obs)
            ? obs  + ((size_t)t1 * N + agent) * 2
            : pred + ((size_t)(t1 - T_obs) * N + agent) * 2;
        float x0 = f0[0], x1 = f1[0];
        float y0 = f0[1], y1 = f1[1];
        bool m = !(isnan(x0) || isnan(x1));
        s_vmt[a * MAXSTEPS + t] = make_float4(m ? (x1 - x0) : 0.f,
                                              m ? (y1 - y0) : 0.f,
                                              m ? 1.f : 0.f, 0.f);
    }

    // (b) W1 / W2 pitched staging for the MLP tail
    #pragma unroll
    for (int k = 0; k < 4; k++) {
        int i = tid + 512 * k;
        float4 v = ((const float4*)W1)[i];
        int row = i >> 5;
        int col = (i & 31) << 2;
        float* p = W1s + row * PW1 + col;
        p[0] = v.x; p[1] = v.y; p[2] = v.z; p[3] = v.w;
    }
    {
        int i = tid;
        float4 v = ((const float4*)W2)[i];
        int row = i >> 4;
        int col = (i & 15) << 2;
        float* p = W2s + row * PW2 + col;
        p[0] = v.x; p[1] = v.y; p[2] = v.z; p[3] = v.w;
    }
    // (c) zero both h ping-pong buffers
    ((uint32_t*)Xs)[tid]       = 0u;
    ((uint32_t*)Xs)[tid + 512] = 0u;

    // ===== wait for prep outputs (weight transforms only) ==================
    cudaGridDependencySynchronize();

    // A fragments straight into registers (16 coalesced LDG.128)
    uint4 A0v[8], A1v[8];
    #pragma unroll
    for (int kc = 0; kc < 8; kc++) A0v[kc] = g_Afrag[kc * 512 + tid];
    #pragma unroll
    for (int kc = 0; kc < 8; kc++) A1v[kc] = g_Afrag[(8 + kc) * 512 + tid];

    // folded input coefficients (L2-hot, quad-broadcast)
    float wc0[4], wc1[4], bcr[4];
    #pragma unroll
    for (int g = 0; g < 4; g++) {
        float4 wc = g_wc[g * 128 + u];
        wc0[g] = wc.x; wc1[g] = wc.y; bcr[g] = wc.z;
    }

    __syncthreads();   // the ONE prologue barrier (vmt/Xs/W staging visible)

    float c0 = 0.f, h0 = 0.f;           // single cell: (agent q, unit u)

    const uint32_t xs_base = (uint32_t)__cvta_generic_to_shared(Xs);
    const uint32_t ldm_off = xs_base + lane * 16;
    const uint32_t sts_off = xs_base + u * 16 + q * 4;
    const float4*  vmt_a   = s_vmt + q * MAXSTEPS;

    // =========================== recurrence ===============================
    #pragma unroll 1
    for (int t = 0; t < steps; t++) {
        const int cur = t & 1;

        float4 vm = vmt_a[t];
        const bool m = (vm.z != 0.f);
        float s_i = fmaf(vm.x, wc0[0], fmaf(vm.y, wc1[0], bcr[0]));
        float s_f = fmaf(vm.x, wc0[1], fmaf(vm.y, wc1[1], bcr[1]));
        float s_g = fmaf(vm.x, wc0[2], fmaf(vm.y, wc1[2], bcr[2]));
        float s_o = fmaf(vm.x, wc0[3], fmaf(vm.y, wc1[3], bcr[3]));

        __syncthreads();   // h(t) stores visible

        // load all 4 B chunks upfront (volatile: reads SMEM across barrier)
        uint32_t B[4][4];
        const uint32_t xc = ldm_off + cur * 2048;
        #pragma unroll
        for (int cch = 0; cch < 4; cch++) {
            asm volatile(
                "ldmatrix.sync.aligned.m8n8.x4.trans.shared.b16 "
                "{%0,%1,%2,%3}, [%4];"
                : "=r"(B[cch][0]), "=r"(B[cch][1]),
                  "=r"(B[cch][2]), "=r"(B[cch][3])
                : "r"(xc + cch * 512));
        }

        // tile0: gates i (elem 0) and g (elem 2)
        float d0a[4] = { s_i, 0.f, s_g, 0.f };
        float d0b[4] = { 0.f, 0.f, 0.f, 0.f };
        #pragma unroll
        for (int cch = 0; cch < 4; cch++) {
            mma_acc(d0a, (const uint32_t*)&A0v[2 * cch],     B[cch][0], B[cch][1]);
            mma_acc(d0b, (const uint32_t*)&A0v[2 * cch + 1], B[cch][2], B[cch][3]);
        }
        float iv = sigf (d0a[0] + d0b[0]);
        float gv = tanha(d0a[2] + d0b[2]);

        // tile1: gates f (elem 0) and o (elem 2) — scheduler may interleave
        float d1a[4] = { s_f, 0.f, s_o, 0.f };
        float d1b[4] = { 0.f, 0.f, 0.f, 0.f };
        #pragma unroll
        for (int cch = 0; cch < 4; cch++) {
            mma_acc(d1a, (const uint32_t*)&A1v[2 * cch],     B[cch][0], B[cch][1]);
            mma_acc(d1b, (const uint32_t*)&A1v[2 * cch + 1], B[cch][2], B[cch][3]);
        }
        float prod = iv * gv;
        float fv = sigf(d1a[0] + d1b[0]);
        float ov = sigf(d1a[2] + d1b[2]);
        float c2 = fmaf(fv, c0, prod);
        float h2 = ov * tanha(c2);
        if (m) { c0 = c2; h0 = h2; }

        {
            __half hh = __float2half_rn(h0);
            asm volatile("st.shared.b16 [%0], %1;"
                         :: "r"(sts_off + ((cur ^ 1) << 11)),
                            "h"(*(const uint16_t*)&hh));
        }
    }

    // =========================== fused MLP tail ===========================
    sh[q * HID + u] = h0;
    __syncthreads();

    // layer 1: (4 x 128) @ W1^T -> relu
    if (tid < 256) {
        const int u1 = tid & 63;
        const int aa = tid >> 6;
        float acc = b1[u1];
        const float* wr = W1s + u1 * PW1;
        const float* hv = sh + aa * HID;
        #pragma unroll
        for (int k = 0; k < HID; k++) acc = fmaf(wr[k], hv[k], acc);
        s1[aa * 64 + u1] = fmaxf(acc, 0.f);
    }
    __syncthreads();

    // layer 2: (4 x 64) @ W2^T -> relu
    if (tid < 128) {
        const int u2 = tid & 31;
        const int aa = tid >> 5;
        float acc = b2[u2];
        const float* wr = W2s + u2 * PW2;
        const float* xv = s1 + aa * 64;
        #pragma unroll
        for (int k = 0; k < 64; k++) acc = fmaf(wr[k], xv[k], acc);
        s2[aa * 32 + u2] = fmaxf(acc, 0.f);
    }
    __syncthreads();

    // layer 3
    if (tid < AG) {
        float acc = b3[0];
        #pragma unroll
        for (int k = 0; k < 32; k++) acc += W3[k] * s2[tid * 32 + k];
        out[row0 + tid] = fmaxf(acc, 0.f);
    }
}

// ------------------------------- launcher ----------------------------------
extern "C" void kernel_launch(void* const* d_in, const int* in_sizes, int n_in,
                              void* d_out, int out_size) {
    const float* observed   = (const float*)d_in[0];
    const float* prediction = (const float*)d_in[1];
    const void*  bsplit     = d_in[3];
    const float* W_emb      = (const float*)d_in[4];
    const float* b_emb      = (const float*)d_in[5];
    const float* W_ih       = (const float*)d_in[6];
    const float* W_hh       = (const float*)d_in[7];
    const float* b_ih       = (const float*)d_in[8];
    const float* b_hh       = (const float*)d_in[9];
    const float* W1         = (const float*)d_in[10];
    const float* b1         = (const float*)d_in[11];
    const float* W2         = (const float*)d_in[12];
    const float* b2         = (const float*)d_in[13];
    const float* W3         = (const float*)d_in[14];
    const float* b3         = (const float*)d_in[15];
    float* out = (float*)d_out;

    const int N      = in_sizes[2] / 2;               // goals: (N,2)
    const int T_obs  = in_sizes[0] / (2 * N);
    const int T_pred = in_sizes[1] / (2 * N);
    int steps = T_obs + T_pred - 1;
    if (steps > MAXSTEPS) steps = MAXSTEPS;

    // prep grid: 16 (A-frag) + 16 (fold) — weight transforms only
    prep_kernel<<<32, 512>>>(W_emb, b_emb, W_ih, W_hh, b_ih, b_hh);

    cudaFuncSetAttribute(fused_kernel, cudaFuncAttributeMaxDynamicSharedMemorySize,
                         SMEM_TOTAL);

    // PDL: fused launches as soon as prep triggers; it grid-syncs internally
    cudaLaunchConfig_t cfg = {};
    cfg.gridDim  = dim3(NBLK, 1, 1);
    cfg.blockDim = dim3(NTHR, 1, 1);
    cfg.dynamicSmemBytes = SMEM_TOTAL;
    cfg.stream = 0;
    cudaLaunchAttribute attrs[1];
    attrs[0].id = cudaLaunchAttributeProgrammaticStreamSerialization;
    attrs[0].val.programmaticStreamSerializationAllowed = 1;
    cfg.attrs = attrs;
    cfg.numAttrs = 1;
    cudaLaunchKernelEx(&cfg, fused_kernel,
                       observed, prediction, bsplit,
                       W1, b1, W2, b2, W3, b3,
                       out, N, T_obs, steps);
}